// round 11
// baseline (speedup 1.0000x reference)
#include <cuda_runtime.h>
#include <cuda_bf16.h>
#include <cstdint>

// ---------------------------------------------------------------------------
// Problem constants
// ---------------------------------------------------------------------------
#define BATCH   32
#define NAGENT  64
#define BN      2048
#define CIN0    16
#define HW0     30
#define FLAT    7744
#define EDIM    128
#define ADIM    5

// ---------------------------------------------------------------------------
// Scratch (activations between conv stages live in gmem / L2)
// ---------------------------------------------------------------------------
__device__ float g_a0   [ (size_t)BN * 16 * 28 * 28 ];
__device__ float g_a1   [ (size_t)BN * 32 * 26 * 26 ];
__device__ float g_a2   [ (size_t)BN * 16 * 24 * 24 ];
__device__ float g_flat [ (size_t)BN * FLAT ];
__device__ float g_acc0 [ BN * EDIM ];
__device__ float g_h    [ BN * EDIM ];

// ---------------------------------------------------------------------------
// f32x2 packed-math helpers
// ---------------------------------------------------------------------------
typedef unsigned long long u64;

__device__ __forceinline__ u64 pk2(float lo, float hi) {
    u64 r; asm("mov.b64 %0, {%1, %2};" : "=l"(r) : "f"(lo), "f"(hi)); return r;
}
__device__ __forceinline__ u64 pk1(float v) {
    u64 r; asm("mov.b64 %0, {%1, %1};" : "=l"(r) : "f"(v)); return r;
}
__device__ __forceinline__ u64 ffma2(u64 a, u64 b, u64 c) {
    u64 d; asm("fma.rn.f32x2 %0, %1, %2, %3;" : "=l"(d) : "l"(a), "l"(b), "l"(c));
    return d;
}
__device__ __forceinline__ u64 add2(u64 a, u64 b) {
    u64 d; asm("add.rn.f32x2 %0, %1, %2;" : "=l"(d) : "l"(a), "l"(b));
    return d;
}
__device__ __forceinline__ void upk2(u64 v, float& lo, float& hi) {
    asm("mov.b64 {%0, %1}, %2;" : "=f"(lo), "=f"(hi) : "l"(v));
}

// ---------------------------------------------------------------------------
// Per-stage conv kernel (R9 structure, unpadded smem), with DUAL accumulator
// banks to cut the per-pixel FFMA2 dependence chain from 12 to 8 cycles.
//  grid = (BN, CO/COCH), block = (COCH/2)*OHW, ONE item per thread.
// ---------------------------------------------------------------------------
template<int CI, int CO, int COCH, int IHW, int OHW>
__global__ void __launch_bounds__((COCH/2)*OHW)
conv_stage_kernel(const float* __restrict__ in,   // [BN][CI][IHW][IHW]
                  float* __restrict__ out,        // [BN][CO][OHW][OHW]
                  const float* __restrict__ w,    // [CO][CI][9]
                  const float* __restrict__ bias) // [CO]
{
    extern __shared__ float s[];
    u64* wpk = (u64*)(s + CI * IHW * IHW);
    const int agent = blockIdx.x;
    const int coB   = blockIdx.y * COCH;
    const int tid   = threadIdx.x;
    constexpr int NTHR = (COCH / 2) * OHW;
    constexpr int PER  = CI * 9;

    // load input plane (coalesced float4)
    {
        const float4* src = (const float4*)(in + (size_t)agent * (CI * IHW * IHW));
        float4* dst = (float4*)s;
        #pragma unroll 4
        for (int i = tid; i < (CI * IHW * IHW) / 4; i += NTHR) dst[i] = src[i];
    }
    // pack this chunk's weights into u64 channel-pairs
    for (int i = tid; i < (COCH / 2) * PER; i += NTHR) {
        int pair = i / PER;
        int r    = i - pair * PER;
        wpk[i] = pk2(__ldg(&w[(size_t)(coB + 2 * pair    ) * PER + r]),
                     __ldg(&w[(size_t)(coB + 2 * pair + 1) * PER + r]));
    }
    __syncthreads();

    // exactly one work item per thread
    const int co2 = tid / OHW;
    const int y   = tid - co2 * OHW;
    const int co  = coB + 2 * co2;

    u64 accA[OHW], accB[OHW];
    u64 binit = pk2(__ldg(&bias[co]), __ldg(&bias[co + 1]));
    #pragma unroll
    for (int x = 0; x < OHW; x++) { accA[x] = binit; accB[x] = 0ull; }

    const u64* wp0 = wpk + co2 * PER;

    for (int ci = 0; ci < CI; ci++) {
        #pragma unroll
        for (int ky = 0; ky < 3; ky++) {
            const u64* wp = wp0 + ci * 9 + ky * 3;
            u64 W0 = wp[0];
            u64 W1 = wp[1];
            u64 W2 = wp[2];
            const float* r = s + (ci * IHW + y + ky) * IHW;
            u64 b0 = pk1(r[0]);
            u64 b1 = pk1(r[1]);
            #pragma unroll
            for (int x = 0; x < OHW; x++) {
                u64 b2 = pk1(r[x + 2]);
                accA[x] = ffma2(b0, W0, accA[x]);   // chain A #1
                accB[x] = ffma2(b1, W1, accB[x]);   // chain B (independent)
                accA[x] = ffma2(b2, W2, accA[x]);   // chain A #2 (8-cyc chain)
                b0 = b1; b1 = b2;
            }
        }
    }

    float* oA = out + ((size_t)agent * CO + co) * (OHW * OHW) + y * OHW;
    float* oB = oA + OHW * OHW;
    #pragma unroll
    for (int x = 0; x < OHW; x++) {
        float lo, hi; upk2(add2(accA[x], accB[x]), lo, hi);
        oA[x] = fmaxf(lo, 0.0f);
        oB[x] = fmaxf(hi, 0.0f);
    }
}

// ---------------------------------------------------------------------------
// MLP0 split-K (unchanged)
// ---------------------------------------------------------------------------
#define KSPLIT  8
#define KCHUNK  968

__global__ void mlp0_splitk_kernel(const float* __restrict__ A,
                                   const float* __restrict__ W,
                                   float* __restrict__ Cacc)
{
    __shared__ float As[8 * 68];
    __shared__ float Ws[8 * 128];
    const int t  = threadIdx.x;
    const int kz = blockIdx.x;
    const int m0 = blockIdx.y * 64;
    const int kstart = kz * KCHUNK;
    const int tx = t & 31, ty = t >> 5;

    u64 acc[8][2];
    #pragma unroll
    for (int r = 0; r < 8; r++) { acc[r][0] = 0ull; acc[r][1] = 0ull; }

    for (int kk = 0; kk < KCHUNK; kk += 8) {
        __syncthreads();
        {
            int e = t * 2;
            int m = e >> 3, k = e & 7;
            const float* ap = A + (size_t)(m0 + m) * FLAT + kstart + kk + k;
            As[ k      * 68 + m] = ap[0];
            As[(k + 1) * 68 + m] = ap[1];
        }
        {
            int e = t * 4;
            int k = e >> 7, col = e & 127;
            *(float4*)&Ws[k * 128 + col] =
                *(const float4*)&W[(size_t)(kstart + kk + k) * EDIM + col];
        }
        __syncthreads();
        #pragma unroll
        for (int k = 0; k < 8; k++) {
            u64 B0 = *(const u64*)&Ws[k * 128 + tx * 4];
            u64 B1 = *(const u64*)&Ws[k * 128 + tx * 4 + 2];
            float4 a0 = *(float4*)&As[k * 68 + ty * 8];
            float4 a1 = *(float4*)&As[k * 68 + ty * 8 + 4];
            float av[8] = {a0.x,a0.y,a0.z,a0.w,a1.x,a1.y,a1.z,a1.w};
            #pragma unroll
            for (int r = 0; r < 8; r++) {
                u64 ar = pk1(av[r]);
                acc[r][0] = ffma2(ar, B0, acc[r][0]);
                acc[r][1] = ffma2(ar, B1, acc[r][1]);
            }
        }
    }
    #pragma unroll
    for (int r = 0; r < 8; r++) {
        int m = m0 + ty * 8 + r;
        float v0, v1, v2, v3;
        upk2(acc[r][0], v0, v1);
        upk2(acc[r][1], v2, v3);
        atomicAdd(&Cacc[(size_t)m * EDIM + tx * 4 + 0], v0);
        atomicAdd(&Cacc[(size_t)m * EDIM + tx * 4 + 1], v1);
        atomicAdd(&Cacc[(size_t)m * EDIM + tx * 4 + 2], v2);
        atomicAdd(&Cacc[(size_t)m * EDIM + tx * 4 + 3], v3);
    }
}

// ---------------------------------------------------------------------------
// 32-row x 128 GEMM helper (256 threads)
// ---------------------------------------------------------------------------
__device__ __forceinline__ void gemm32(const float* __restrict__ sIn,
                                       float* __restrict__ sOut,
                                       float* __restrict__ sW,
                                       const float* __restrict__ W,
                                       const float* __restrict__ bias,
                                       int relu, int t)
{
    __syncthreads();
    for (int i = t * 4; i < 128 * 128; i += 1024)
        *(float4*)&sW[i] = *(const float4*)&W[i];
    __syncthreads();

    const int tx = t & 31;
    const int ry = (t >> 5) * 4;
    u64 acc[4][2];
    u64 b0i = bias ? pk2(bias[tx*4+0], bias[tx*4+1]) : 0ull;
    u64 b1i = bias ? pk2(bias[tx*4+2], bias[tx*4+3]) : 0ull;
    #pragma unroll
    for (int r = 0; r < 4; r++) { acc[r][0] = b0i; acc[r][1] = b1i; }

    #pragma unroll 4
    for (int k = 0; k < 128; k++) {
        u64 B0 = *(const u64*)&sW[k * 128 + tx * 4];
        u64 B1 = *(const u64*)&sW[k * 128 + tx * 4 + 2];
        #pragma unroll
        for (int r = 0; r < 4; r++) {
            u64 ar = pk1(sIn[(ry + r) * 128 + k]);
            acc[r][0] = ffma2(ar, B0, acc[r][0]);
            acc[r][1] = ffma2(ar, B1, acc[r][1]);
        }
    }
    #pragma unroll
    for (int r = 0; r < 4; r++) {
        float v[4];
        upk2(acc[r][0], v[0], v[1]);
        upk2(acc[r][1], v[2], v[3]);
        #pragma unroll
        for (int c = 0; c < 4; c++)
            if (relu) v[c] = fmaxf(v[c], 0.0f);
        *(float4*)&sOut[(ry + r) * 128 + tx * 4] = *(float4*)v;
    }
}

// ---------------------------------------------------------------------------
// K1: pre-GCN chain, grid = 64, 32-row tiles
// ---------------------------------------------------------------------------
__global__ __launch_bounds__(256, 1)
void pre_gcn_kernel(const float* __restrict__ acc0,
                    const float* __restrict__ mb0,
                    const float* __restrict__ mw1, const float* __restrict__ mb1,
                    const float* __restrict__ mw2, const float* __restrict__ mb2,
                    const float* __restrict__ gw,
                    float* __restrict__ h)
{
    extern __shared__ float s[];
    float* sA = s;
    float* sB = s + 4096;
    float* sW = s + 8192;
    const int t = threadIdx.x;
    const size_t base = (size_t)blockIdx.x * 32 * EDIM;

    for (int i = t; i < 4096; i += 256) {
        int k = i & 127;
        sA[i] = fmaxf(acc0[base + i] + mb0[k], 0.0f);
    }

    gemm32(sA, sB, sW, mw1, mb1, 1, t);
    gemm32(sB, sA, sW, mw2, mb2, 0, t);
    gemm32(sA, sB, sW, gw,  nullptr, 0, t);

    __syncthreads();
    for (int i = t; i < 4096; i += 256) h[base + i] = sB[i];
}

// ---------------------------------------------------------------------------
// K2: GCN aggregation + DQN head, grid = (32, 2)
// ---------------------------------------------------------------------------
__global__ __launch_bounds__(256, 1)
void gcn_tail_kernel(const float* __restrict__ h,
                     const float* __restrict__ gb,
                     const float* __restrict__ fw0, const float* __restrict__ fb0,
                     const float* __restrict__ fw1, const float* __restrict__ fb1,
                     const float* __restrict__ fw2, const float* __restrict__ fb2,
                     const float* __restrict__ adj,
                     const int* __restrict__ inact,
                     float* __restrict__ out)
{
    extern __shared__ float s[];
    float* sH = s;
    float* sX = s + 8192;
    float* sY = s + 12288;
    float* sW = s + 16384;
    const int b = blockIdx.x, t = threadIdx.x;
    const int j0 = blockIdx.y * 32;
    const size_t row0 = (size_t)b * NAGENT;

    for (int i = t; i < 8192; i += 256) sH[i] = h[row0 * EDIM + i];
    for (int i = t; i < 4096; i += 256) sW[i] = adj[(size_t)b * 4096 + i];
    __syncthreads();
    if (t < 64) {
        float d = 0.f;
        for (int i = 0; i < 64; i++) d += sW[i * 64 + t];
        sW[4096 + t] = (d > 0.f) ? rsqrtf(fmaxf(d, 1e-30f)) : 0.f;
    }
    __syncthreads();
    for (int i = t; i < 4096; i += 256) {
        int r = i >> 6, c = i & 63;
        sW[i] *= sW[4096 + r] * sW[4096 + c];
    }
    __syncthreads();
    for (int o = t; o < 4096; o += 256) {
        int jl = o >> 7, d = o & 127;
        int j = j0 + jl;
        float a = gb[d];
        #pragma unroll 8
        for (int i = 0; i < 64; i++)
            a = fmaf(sW[i * 64 + j], sH[i * 128 + d], a);
        sX[o] = a;
    }

    gemm32(sX, sY, sW, fw0, fb0, 1, t);
    gemm32(sY, sX, sW, fw1, fb1, 1, t);

    __syncthreads();
    for (int p = t; p < 32 * ADIM; p += 256) {
        int row = p / ADIM, a = p - row * ADIM;
        float acc = fb2[a];
        #pragma unroll 8
        for (int k = 0; k < EDIM; k++)
            acc = fmaf(sX[row * 128 + k], __ldg(&fw2[k * ADIM + a]), acc);
        size_t grow = row0 + j0 + row;
        bool z = (inact[grow] != 0);
        out[grow * ADIM + a] = z ? 0.f : acc;
    }
}

__global__ void zero_kernel(float* __restrict__ p, int n)
{
    int i = blockIdx.x * blockDim.x + threadIdx.x;
    if (i < n) p[i] = 0.f;
}

// ---------------------------------------------------------------------------
// Launch
// ---------------------------------------------------------------------------
extern "C" void kernel_launch(void* const* d_in, const int* in_sizes, int n_in,
                              void* d_out, int out_size)
{
    (void)in_sizes; (void)n_in; (void)out_size;
    const float* states = (const float*)d_in[0];
    const float* adj    = (const float*)d_in[1];
    const int*   inact  = (const int*)d_in[2];
    const float* cw0 = (const float*)d_in[3];  const float* cb0 = (const float*)d_in[4];
    const float* cw1 = (const float*)d_in[5];  const float* cb1 = (const float*)d_in[6];
    const float* cw2 = (const float*)d_in[7];  const float* cb2 = (const float*)d_in[8];
    const float* cw3 = (const float*)d_in[9];  const float* cb3 = (const float*)d_in[10];
    const float* mw0 = (const float*)d_in[11]; const float* mb0 = (const float*)d_in[12];
    const float* mw1 = (const float*)d_in[13]; const float* mb1 = (const float*)d_in[14];
    const float* mw2 = (const float*)d_in[15]; const float* mb2 = (const float*)d_in[16];
    const float* gw  = (const float*)d_in[17]; const float* gb  = (const float*)d_in[18];
    const float* fw0 = (const float*)d_in[19]; const float* fb0 = (const float*)d_in[20];
    const float* fw1 = (const float*)d_in[21]; const float* fb1 = (const float*)d_in[22];
    const float* fw2 = (const float*)d_in[23]; const float* fb2 = (const float*)d_in[24];
    float* out = (float*)d_out;

    float *p_a0, *p_a1, *p_a2, *p_flat, *p_acc0, *p_h;
    cudaGetSymbolAddress((void**)&p_a0,   g_a0);
    cudaGetSymbolAddress((void**)&p_a1,   g_a1);
    cudaGetSymbolAddress((void**)&p_a2,   g_a2);
    cudaGetSymbolAddress((void**)&p_flat, g_flat);
    cudaGetSymbolAddress((void**)&p_acc0, g_acc0);
    cudaGetSymbolAddress((void**)&p_h,    g_h);

    // per-stage smem: input plane + packed weight chunk (R9 layout, unpadded)
    const int smem0 = 16*30*30*4 + (8*16*9)*8;   // 66816
    const int smem1 = 16*28*28*4 + (8*16*9)*8;   // 59392
    const int smem2 = 32*26*26*4 + (8*32*9)*8;   // 104960
    const int smem3 = 16*24*24*4 + (8*16*9)*8;   // 46080
    const int preSmem  = (4096 + 4096 + 16384) * 4;
    const int tailSmem = (8192 + 4096 + 4096 + 16384) * 4;

    cudaFuncSetAttribute((const void*)conv_stage_kernel<16,16,16,30,28>,
                         cudaFuncAttributeMaxDynamicSharedMemorySize, smem0);
    cudaFuncSetAttribute((const void*)conv_stage_kernel<16,32,16,28,26>,
                         cudaFuncAttributeMaxDynamicSharedMemorySize, smem1);
    cudaFuncSetAttribute((const void*)conv_stage_kernel<32,16,16,26,24>,
                         cudaFuncAttributeMaxDynamicSharedMemorySize, smem2);
    cudaFuncSetAttribute((const void*)conv_stage_kernel<16,16,16,24,22>,
                         cudaFuncAttributeMaxDynamicSharedMemorySize, smem3);
    cudaFuncSetAttribute(pre_gcn_kernel,  cudaFuncAttributeMaxDynamicSharedMemorySize, preSmem);
    cudaFuncSetAttribute(gcn_tail_kernel, cudaFuncAttributeMaxDynamicSharedMemorySize, tailSmem);

    zero_kernel<<<(BN*EDIM + 255)/256, 256>>>(p_acc0, BN*EDIM);

    // conv stages (one item per thread; block = (COCH/2)*OHW)
    conv_stage_kernel<16,16,16,30,28><<<dim3(BN,1), 224, smem0>>>(states, p_a0, cw0, cb0);
    conv_stage_kernel<16,32,16,28,26><<<dim3(BN,2), 208, smem1>>>(p_a0,   p_a1, cw1, cb1);
    conv_stage_kernel<32,16,16,26,24><<<dim3(BN,1), 192, smem2>>>(p_a1,   p_a2, cw2, cb2);
    conv_stage_kernel<16,16,16,24,22><<<dim3(BN,1), 176, smem3>>>(p_a2, p_flat, cw3, cb3);

    mlp0_splitk_kernel<<<dim3(KSPLIT, BN/64), 256>>>(p_flat, mw0, p_acc0);

    pre_gcn_kernel<<<BN/32, 256, preSmem>>>(p_acc0, mb0, mw1, mb1, mw2, mb2, gw, p_h);

    gcn_tail_kernel<<<dim3(BATCH, 2), 256, tailSmem>>>(p_h, gb, fw0, fb0, fw1, fb1,
                                                       fw2, fb2, adj, inact, out);
}

// round 12
// speedup vs baseline: 1.5303x; 1.5303x over previous
#include <cuda_runtime.h>
#include <cuda_bf16.h>
#include <cstdint>

// ---------------------------------------------------------------------------
// Problem constants
// ---------------------------------------------------------------------------
#define BATCH   32
#define NAGENT  64
#define BN      2048
#define CIN0    16
#define HW0     30
#define FLAT    7744
#define EDIM    128
#define ADIM    5

// ---------------------------------------------------------------------------
// Scratch (activations between conv stages live in gmem / L2)
// ---------------------------------------------------------------------------
__device__ float g_a0   [ (size_t)BN * 16 * 28 * 28 ];
__device__ float g_a1   [ (size_t)BN * 32 * 26 * 26 ];
__device__ float g_a2   [ (size_t)BN * 16 * 24 * 24 ];
__device__ float g_flat [ (size_t)BN * FLAT ];
__device__ float g_acc0 [ BN * EDIM ];
__device__ float g_h    [ BN * EDIM ];

// ---------------------------------------------------------------------------
// f32x2 packed-math helpers
// ---------------------------------------------------------------------------
typedef unsigned long long u64;

__device__ __forceinline__ u64 pk2(float lo, float hi) {
    u64 r; asm("mov.b64 %0, {%1, %2};" : "=l"(r) : "f"(lo), "f"(hi)); return r;
}
__device__ __forceinline__ u64 pk1(float v) {
    u64 r; asm("mov.b64 %0, {%1, %1};" : "=l"(r) : "f"(v)); return r;
}
__device__ __forceinline__ u64 ffma2(u64 a, u64 b, u64 c) {
    u64 d; asm("fma.rn.f32x2 %0, %1, %2, %3;" : "=l"(d) : "l"(a), "l"(b), "l"(c));
    return d;
}
__device__ __forceinline__ void upk2(u64 v, float& lo, float& hi) {
    asm("mov.b64 {%0, %1}, %2;" : "=f"(lo), "=f"(hi) : "l"(v));
}

// ---------------------------------------------------------------------------
// Per-stage conv kernel (R9 body) with STAGED, COALESCED output writes.
//  Phase 1: coalesced load of input plane to smem; pack weight chunk.
//  Phase 2: accumulate in registers (one item per thread).
//  Phase 3: sync; scatter accumulators into the (now dead) input smem in
//           dense [co_local][y][x] layout; sync; coalesced float4 store.
//  grid = (BN, CO/COCH), block = (COCH/2)*OHW.
// ---------------------------------------------------------------------------
template<int CI, int CO, int COCH, int IHW, int OHW>
__global__ void __launch_bounds__((COCH/2)*OHW)
conv_stage_kernel(const float* __restrict__ in,   // [BN][CI][IHW][IHW]
                  float* __restrict__ out,        // [BN][CO][OHW][OHW]
                  const float* __restrict__ w,    // [CO][CI][9]
                  const float* __restrict__ bias) // [CO]
{
    extern __shared__ float s[];
    u64* wpk = (u64*)(s + CI * IHW * IHW);
    const int agent = blockIdx.x;
    const int coB   = blockIdx.y * COCH;
    const int tid   = threadIdx.x;
    constexpr int NTHR = (COCH / 2) * OHW;
    constexpr int PER  = CI * 9;
    static_assert(COCH * OHW * OHW <= CI * IHW * IHW, "output must fit input region");

    // Phase 1: load input plane (coalesced float4) + pack weights
    {
        const float4* src = (const float4*)(in + (size_t)agent * (CI * IHW * IHW));
        float4* dst = (float4*)s;
        #pragma unroll 4
        for (int i = tid; i < (CI * IHW * IHW) / 4; i += NTHR) dst[i] = src[i];
    }
    for (int i = tid; i < (COCH / 2) * PER; i += NTHR) {
        int pair = i / PER;
        int r    = i - pair * PER;
        wpk[i] = pk2(__ldg(&w[(size_t)(coB + 2 * pair    ) * PER + r]),
                     __ldg(&w[(size_t)(coB + 2 * pair + 1) * PER + r]));
    }
    __syncthreads();

    // Phase 2: accumulate (one item per thread)
    const int co2 = tid / OHW;
    const int y   = tid - co2 * OHW;

    u64 acc[OHW];
    u64 binit = pk2(__ldg(&bias[coB + 2 * co2]), __ldg(&bias[coB + 2 * co2 + 1]));
    #pragma unroll
    for (int x = 0; x < OHW; x++) acc[x] = binit;

    const u64* wp0 = wpk + co2 * PER;

    for (int ci = 0; ci < CI; ci++) {
        #pragma unroll
        for (int ky = 0; ky < 3; ky++) {
            const u64* wp = wp0 + ci * 9 + ky * 3;
            u64 W0 = wp[0];
            u64 W1 = wp[1];
            u64 W2 = wp[2];
            const float* r = s + (ci * IHW + y + ky) * IHW;
            u64 b0 = pk1(r[0]);
            u64 b1 = pk1(r[1]);
            #pragma unroll
            for (int x = 0; x < OHW; x++) {
                u64 b2 = pk1(r[x + 2]);
                acc[x] = ffma2(b0, W0, acc[x]);
                acc[x] = ffma2(b1, W1, acc[x]);
                acc[x] = ffma2(b2, W2, acc[x]);
                b0 = b1; b1 = b2;
            }
        }
    }

    // Phase 3: stage outputs in smem, then coalesced store
    __syncthreads();   // everyone done reading input smem
    {
        float* oA = s + (2 * co2 * OHW + y) * OHW;
        float* oB = s + ((2 * co2 + 1) * OHW + y) * OHW;
        #pragma unroll
        for (int x = 0; x < OHW; x++) {
            float lo, hi; upk2(acc[x], lo, hi);
            oA[x] = fmaxf(lo, 0.0f);
            oB[x] = fmaxf(hi, 0.0f);
        }
    }
    __syncthreads();
    {
        float4* og = (float4*)(out + ((size_t)agent * CO + coB) * (OHW * OHW));
        const float4* osrc = (const float4*)s;
        #pragma unroll 4
        for (int i = tid; i < (COCH * OHW * OHW) / 4; i += NTHR) og[i] = osrc[i];
    }
}

// ---------------------------------------------------------------------------
// MLP0 split-K (unchanged)
// ---------------------------------------------------------------------------
#define KSPLIT  8
#define KCHUNK  968

__global__ void mlp0_splitk_kernel(const float* __restrict__ A,
                                   const float* __restrict__ W,
                                   float* __restrict__ Cacc)
{
    __shared__ float As[8 * 68];
    __shared__ float Ws[8 * 128];
    const int t  = threadIdx.x;
    const int kz = blockIdx.x;
    const int m0 = blockIdx.y * 64;
    const int kstart = kz * KCHUNK;
    const int tx = t & 31, ty = t >> 5;

    u64 acc[8][2];
    #pragma unroll
    for (int r = 0; r < 8; r++) { acc[r][0] = 0ull; acc[r][1] = 0ull; }

    for (int kk = 0; kk < KCHUNK; kk += 8) {
        __syncthreads();
        {
            int e = t * 2;
            int m = e >> 3, k = e & 7;
            const float* ap = A + (size_t)(m0 + m) * FLAT + kstart + kk + k;
            As[ k      * 68 + m] = ap[0];
            As[(k + 1) * 68 + m] = ap[1];
        }
        {
            int e = t * 4;
            int k = e >> 7, col = e & 127;
            *(float4*)&Ws[k * 128 + col] =
                *(const float4*)&W[(size_t)(kstart + kk + k) * EDIM + col];
        }
        __syncthreads();
        #pragma unroll
        for (int k = 0; k < 8; k++) {
            u64 B0 = *(const u64*)&Ws[k * 128 + tx * 4];
            u64 B1 = *(const u64*)&Ws[k * 128 + tx * 4 + 2];
            float4 a0 = *(float4*)&As[k * 68 + ty * 8];
            float4 a1 = *(float4*)&As[k * 68 + ty * 8 + 4];
            float av[8] = {a0.x,a0.y,a0.z,a0.w,a1.x,a1.y,a1.z,a1.w};
            #pragma unroll
            for (int r = 0; r < 8; r++) {
                u64 ar = pk1(av[r]);
                acc[r][0] = ffma2(ar, B0, acc[r][0]);
                acc[r][1] = ffma2(ar, B1, acc[r][1]);
            }
        }
    }
    #pragma unroll
    for (int r = 0; r < 8; r++) {
        int m = m0 + ty * 8 + r;
        float v0, v1, v2, v3;
        upk2(acc[r][0], v0, v1);
        upk2(acc[r][1], v2, v3);
        atomicAdd(&Cacc[(size_t)m * EDIM + tx * 4 + 0], v0);
        atomicAdd(&Cacc[(size_t)m * EDIM + tx * 4 + 1], v1);
        atomicAdd(&Cacc[(size_t)m * EDIM + tx * 4 + 2], v2);
        atomicAdd(&Cacc[(size_t)m * EDIM + tx * 4 + 3], v3);
    }
}

// ---------------------------------------------------------------------------
// 32-row x 128 GEMM helper (256 threads)
// ---------------------------------------------------------------------------
__device__ __forceinline__ void gemm32(const float* __restrict__ sIn,
                                       float* __restrict__ sOut,
                                       float* __restrict__ sW,
                                       const float* __restrict__ W,
                                       const float* __restrict__ bias,
                                       int relu, int t)
{
    __syncthreads();
    for (int i = t * 4; i < 128 * 128; i += 1024)
        *(float4*)&sW[i] = *(const float4*)&W[i];
    __syncthreads();

    const int tx = t & 31;
    const int ry = (t >> 5) * 4;
    u64 acc[4][2];
    u64 b0i = bias ? pk2(bias[tx*4+0], bias[tx*4+1]) : 0ull;
    u64 b1i = bias ? pk2(bias[tx*4+2], bias[tx*4+3]) : 0ull;
    #pragma unroll
    for (int r = 0; r < 4; r++) { acc[r][0] = b0i; acc[r][1] = b1i; }

    #pragma unroll 4
    for (int k = 0; k < 128; k++) {
        u64 B0 = *(const u64*)&sW[k * 128 + tx * 4];
        u64 B1 = *(const u64*)&sW[k * 128 + tx * 4 + 2];
        #pragma unroll
        for (int r = 0; r < 4; r++) {
            u64 ar = pk1(sIn[(ry + r) * 128 + k]);
            acc[r][0] = ffma2(ar, B0, acc[r][0]);
            acc[r][1] = ffma2(ar, B1, acc[r][1]);
        }
    }
    #pragma unroll
    for (int r = 0; r < 4; r++) {
        float v[4];
        upk2(acc[r][0], v[0], v[1]);
        upk2(acc[r][1], v[2], v[3]);
        #pragma unroll
        for (int c = 0; c < 4; c++)
            if (relu) v[c] = fmaxf(v[c], 0.0f);
        *(float4*)&sOut[(ry + r) * 128 + tx * 4] = *(float4*)v;
    }
}

// ---------------------------------------------------------------------------
// K1: pre-GCN chain, grid = 64, 32-row tiles
// ---------------------------------------------------------------------------
__global__ __launch_bounds__(256, 1)
void pre_gcn_kernel(const float* __restrict__ acc0,
                    const float* __restrict__ mb0,
                    const float* __restrict__ mw1, const float* __restrict__ mb1,
                    const float* __restrict__ mw2, const float* __restrict__ mb2,
                    const float* __restrict__ gw,
                    float* __restrict__ h)
{
    extern __shared__ float s[];
    float* sA = s;
    float* sB = s + 4096;
    float* sW = s + 8192;
    const int t = threadIdx.x;
    const size_t base = (size_t)blockIdx.x * 32 * EDIM;

    for (int i = t; i < 4096; i += 256) {
        int k = i & 127;
        sA[i] = fmaxf(acc0[base + i] + mb0[k], 0.0f);
    }

    gemm32(sA, sB, sW, mw1, mb1, 1, t);
    gemm32(sB, sA, sW, mw2, mb2, 0, t);
    gemm32(sA, sB, sW, gw,  nullptr, 0, t);

    __syncthreads();
    for (int i = t; i < 4096; i += 256) h[base + i] = sB[i];
}

// ---------------------------------------------------------------------------
// K2: GCN aggregation + DQN head, grid = (32, 2)
// ---------------------------------------------------------------------------
__global__ __launch_bounds__(256, 1)
void gcn_tail_kernel(const float* __restrict__ h,
                     const float* __restrict__ gb,
                     const float* __restrict__ fw0, const float* __restrict__ fb0,
                     const float* __restrict__ fw1, const float* __restrict__ fb1,
                     const float* __restrict__ fw2, const float* __restrict__ fb2,
                     const float* __restrict__ adj,
                     const int* __restrict__ inact,
                     float* __restrict__ out)
{
    extern __shared__ float s[];
    float* sH = s;
    float* sX = s + 8192;
    float* sY = s + 12288;
    float* sW = s + 16384;
    const int b = blockIdx.x, t = threadIdx.x;
    const int j0 = blockIdx.y * 32;
    const size_t row0 = (size_t)b * NAGENT;

    for (int i = t; i < 8192; i += 256) sH[i] = h[row0 * EDIM + i];
    for (int i = t; i < 4096; i += 256) sW[i] = adj[(size_t)b * 4096 + i];
    __syncthreads();
    if (t < 64) {
        float d = 0.f;
        for (int i = 0; i < 64; i++) d += sW[i * 64 + t];
        sW[4096 + t] = (d > 0.f) ? rsqrtf(fmaxf(d, 1e-30f)) : 0.f;
    }
    __syncthreads();
    for (int i = t; i < 4096; i += 256) {
        int r = i >> 6, c = i & 63;
        sW[i] *= sW[4096 + r] * sW[4096 + c];
    }
    __syncthreads();
    for (int o = t; o < 4096; o += 256) {
        int jl = o >> 7, d = o & 127;
        int j = j0 + jl;
        float a = gb[d];
        #pragma unroll 8
        for (int i = 0; i < 64; i++)
            a = fmaf(sW[i * 64 + j], sH[i * 128 + d], a);
        sX[o] = a;
    }

    gemm32(sX, sY, sW, fw0, fb0, 1, t);
    gemm32(sY, sX, sW, fw1, fb1, 1, t);

    __syncthreads();
    for (int p = t; p < 32 * ADIM; p += 256) {
        int row = p / ADIM, a = p - row * ADIM;
        float acc = fb2[a];
        #pragma unroll 8
        for (int k = 0; k < EDIM; k++)
            acc = fmaf(sX[row * 128 + k], __ldg(&fw2[k * ADIM + a]), acc);
        size_t grow = row0 + j0 + row;
        bool z = (inact[grow] != 0);
        out[grow * ADIM + a] = z ? 0.f : acc;
    }
}

__global__ void zero_kernel(float* __restrict__ p, int n)
{
    int i = blockIdx.x * blockDim.x + threadIdx.x;
    if (i < n) p[i] = 0.f;
}

// ---------------------------------------------------------------------------
// Launch
// ---------------------------------------------------------------------------
extern "C" void kernel_launch(void* const* d_in, const int* in_sizes, int n_in,
                              void* d_out, int out_size)
{
    (void)in_sizes; (void)n_in; (void)out_size;
    const float* states = (const float*)d_in[0];
    const float* adj    = (const float*)d_in[1];
    const int*   inact  = (const int*)d_in[2];
    const float* cw0 = (const float*)d_in[3];  const float* cb0 = (const float*)d_in[4];
    const float* cw1 = (const float*)d_in[5];  const float* cb1 = (const float*)d_in[6];
    const float* cw2 = (const float*)d_in[7];  const float* cb2 = (const float*)d_in[8];
    const float* cw3 = (const float*)d_in[9];  const float* cb3 = (const float*)d_in[10];
    const float* mw0 = (const float*)d_in[11]; const float* mb0 = (const float*)d_in[12];
    const float* mw1 = (const float*)d_in[13]; const float* mb1 = (const float*)d_in[14];
    const float* mw2 = (const float*)d_in[15]; const float* mb2 = (const float*)d_in[16];
    const float* gw  = (const float*)d_in[17]; const float* gb  = (const float*)d_in[18];
    const float* fw0 = (const float*)d_in[19]; const float* fb0 = (const float*)d_in[20];
    const float* fw1 = (const float*)d_in[21]; const float* fb1 = (const float*)d_in[22];
    const float* fw2 = (const float*)d_in[23]; const float* fb2 = (const float*)d_in[24];
    float* out = (float*)d_out;

    float *p_a0, *p_a1, *p_a2, *p_flat, *p_acc0, *p_h;
    cudaGetSymbolAddress((void**)&p_a0,   g_a0);
    cudaGetSymbolAddress((void**)&p_a1,   g_a1);
    cudaGetSymbolAddress((void**)&p_a2,   g_a2);
    cudaGetSymbolAddress((void**)&p_flat, g_flat);
    cudaGetSymbolAddress((void**)&p_acc0, g_acc0);
    cudaGetSymbolAddress((void**)&p_h,    g_h);

    // per-stage smem: input plane + packed weight chunk (R9 sizes)
    const int smem0 = 16*30*30*4 + (8*16*9)*8;   // 66816
    const int smem1 = 16*28*28*4 + (8*16*9)*8;   // 59392
    const int smem2 = 32*26*26*4 + (8*32*9)*8;   // 104960
    const int smem3 = 16*24*24*4 + (8*16*9)*8;   // 46080
    const int preSmem  = (4096 + 4096 + 16384) * 4;
    const int tailSmem = (8192 + 4096 + 4096 + 16384) * 4;

    cudaFuncSetAttribute((const void*)conv_stage_kernel<16,16,16,30,28>,
                         cudaFuncAttributeMaxDynamicSharedMemorySize, smem0);
    cudaFuncSetAttribute((const void*)conv_stage_kernel<16,32,16,28,26>,
                         cudaFuncAttributeMaxDynamicSharedMemorySize, smem1);
    cudaFuncSetAttribute((const void*)conv_stage_kernel<32,16,16,26,24>,
                         cudaFuncAttributeMaxDynamicSharedMemorySize, smem2);
    cudaFuncSetAttribute((const void*)conv_stage_kernel<16,16,16,24,22>,
                         cudaFuncAttributeMaxDynamicSharedMemorySize, smem3);
    cudaFuncSetAttribute(pre_gcn_kernel,  cudaFuncAttributeMaxDynamicSharedMemorySize, preSmem);
    cudaFuncSetAttribute(gcn_tail_kernel, cudaFuncAttributeMaxDynamicSharedMemorySize, tailSmem);

    zero_kernel<<<(BN*EDIM + 255)/256, 256>>>(p_acc0, BN*EDIM);

    // conv stages (one item per thread; staged coalesced output)
    conv_stage_kernel<16,16,16,30,28><<<dim3(BN,1), 224, smem0>>>(states, p_a0, cw0, cb0);
    conv_stage_kernel<16,32,16,28,26><<<dim3(BN,2), 208, smem1>>>(p_a0,   p_a1, cw1, cb1);
    conv_stage_kernel<32,16,16,26,24><<<dim3(BN,1), 192, smem2>>>(p_a1,   p_a2, cw2, cb2);
    conv_stage_kernel<16,16,16,24,22><<<dim3(BN,1), 176, smem3>>>(p_a2, p_flat, cw3, cb3);

    mlp0_splitk_kernel<<<dim3(KSPLIT, BN/64), 256>>>(p_flat, mw0, p_acc0);

    pre_gcn_kernel<<<BN/32, 256, preSmem>>>(p_acc0, mb0, mw1, mb1, mw2, mb2, gw, p_h);

    gcn_tail_kernel<<<dim3(BATCH, 2), 256, tailSmem>>>(p_h, gb, fw0, fb0, fw1, fb1,
                                                       fw2, fb2, adj, inact, out);
}

// round 13
// speedup vs baseline: 1.5987x; 1.0447x over previous
#include <cuda_runtime.h>
#include <cuda_bf16.h>
#include <cstdint>

// ---------------------------------------------------------------------------
// Problem constants
// ---------------------------------------------------------------------------
#define BATCH   32
#define NAGENT  64
#define BN      2048
#define CIN0    16
#define HW0     30
#define FLAT    7744
#define EDIM    128
#define ADIM    5

// ---------------------------------------------------------------------------
// Scratch (activations between conv stages live in gmem / L2)
// ---------------------------------------------------------------------------
__device__ float g_a0   [ (size_t)BN * 16 * 28 * 28 ];
__device__ float g_a1   [ (size_t)BN * 32 * 26 * 26 ];
__device__ float g_a2   [ (size_t)BN * 16 * 24 * 24 ];
__device__ float g_flat [ (size_t)BN * FLAT ];
__device__ float g_acc0 [ BN * EDIM ];
__device__ float g_h    [ BN * EDIM ];

// ---------------------------------------------------------------------------
// f32x2 packed-math helpers
// ---------------------------------------------------------------------------
typedef unsigned long long u64;

__device__ __forceinline__ u64 pk2(float lo, float hi) {
    u64 r; asm("mov.b64 %0, {%1, %2};" : "=l"(r) : "f"(lo), "f"(hi)); return r;
}
__device__ __forceinline__ u64 pk1(float v) {
    u64 r; asm("mov.b64 %0, {%1, %1};" : "=l"(r) : "f"(v)); return r;
}
__device__ __forceinline__ u64 ffma2(u64 a, u64 b, u64 c) {
    u64 d; asm("fma.rn.f32x2 %0, %1, %2, %3;" : "=l"(d) : "l"(a), "l"(b), "l"(c));
    return d;
}
__device__ __forceinline__ void upk2(u64 v, float& lo, float& hi) {
    asm("mov.b64 {%0, %1}, %2;" : "=f"(lo), "=f"(hi) : "l"(v));
}

// ---------------------------------------------------------------------------
// Per-stage conv kernel (R12 structure) with LDS.64 pixel-pair input loads:
// one aligned 8-byte smem load feeds TWO output pixels (halves smem
// wavefront traffic, the measured bottleneck).
//  grid = (BN, CO/COCH), block = (COCH/2)*OHW, ONE item per thread.
// ---------------------------------------------------------------------------
template<int CI, int CO, int COCH, int IHW, int OHW>
__global__ void __launch_bounds__((COCH/2)*OHW)
conv_stage_kernel(const float* __restrict__ in,   // [BN][CI][IHW][IHW]
                  float* __restrict__ out,        // [BN][CO][OHW][OHW]
                  const float* __restrict__ w,    // [CO][CI][9]
                  const float* __restrict__ bias) // [CO]
{
    extern __shared__ float s[];
    u64* wpk = (u64*)(s + CI * IHW * IHW);
    const int agent = blockIdx.x;
    const int coB   = blockIdx.y * COCH;
    const int tid   = threadIdx.x;
    constexpr int NTHR = (COCH / 2) * OHW;
    constexpr int PER  = CI * 9;
    static_assert(COCH * OHW * OHW <= CI * IHW * IHW, "output must fit input region");
    static_assert((IHW % 2) == 0 && (OHW % 2) == 0, "pair loads need even sizes");

    // Phase 1: load input plane (coalesced float4) + pack weights
    {
        const float4* src = (const float4*)(in + (size_t)agent * (CI * IHW * IHW));
        float4* dst = (float4*)s;
        #pragma unroll 4
        for (int i = tid; i < (CI * IHW * IHW) / 4; i += NTHR) dst[i] = src[i];
    }
    for (int i = tid; i < (COCH / 2) * PER; i += NTHR) {
        int pair = i / PER;
        int r    = i - pair * PER;
        wpk[i] = pk2(__ldg(&w[(size_t)(coB + 2 * pair    ) * PER + r]),
                     __ldg(&w[(size_t)(coB + 2 * pair + 1) * PER + r]));
    }
    __syncthreads();

    // Phase 2: accumulate (one item per thread)
    const int co2 = tid / OHW;
    const int y   = tid - co2 * OHW;

    u64 acc[OHW];
    u64 binit = pk2(__ldg(&bias[coB + 2 * co2]), __ldg(&bias[coB + 2 * co2 + 1]));
    #pragma unroll
    for (int x = 0; x < OHW; x++) acc[x] = binit;

    const u64* wp0 = wpk + co2 * PER;

    for (int ci = 0; ci < CI; ci++) {
        #pragma unroll
        for (int ky = 0; ky < 3; ky++) {
            const u64* wp = wp0 + ci * 9 + ky * 3;
            u64 W0 = wp[0];
            u64 W1 = wp[1];
            u64 W2 = wp[2];
            const float* r = s + (ci * IHW + y + ky) * IHW;
            // initial pair {r[0], r[1]} via one aligned LDS.64
            u64 p0 = *(const u64*)&r[0];
            float f0, f1; upk2(p0, f0, f1);
            u64 b0 = pk1(f0);
            u64 b1 = pk1(f1);
            #pragma unroll
            for (int x = 0; x < OHW; x += 2) {
                // one LDS.64 feeds pixels x and x+1
                u64 pr = *(const u64*)&r[x + 2];
                float g0, g1; upk2(pr, g0, g1);
                u64 b2a = pk1(g0);          // r[x+2]
                u64 b2b = pk1(g1);          // r[x+3]
                acc[x]   = ffma2(b0,  W0, acc[x]);
                acc[x]   = ffma2(b1,  W1, acc[x]);
                acc[x]   = ffma2(b2a, W2, acc[x]);
                acc[x+1] = ffma2(b1,  W0, acc[x+1]);
                acc[x+1] = ffma2(b2a, W1, acc[x+1]);
                acc[x+1] = ffma2(b2b, W2, acc[x+1]);
                b0 = b2a; b1 = b2b;
            }
        }
    }

    // Phase 3: stage outputs in smem, then coalesced store
    __syncthreads();
    {
        float* oA = s + (2 * co2 * OHW + y) * OHW;
        float* oB = s + ((2 * co2 + 1) * OHW + y) * OHW;
        #pragma unroll
        for (int x = 0; x < OHW; x++) {
            float lo, hi; upk2(acc[x], lo, hi);
            oA[x] = fmaxf(lo, 0.0f);
            oB[x] = fmaxf(hi, 0.0f);
        }
    }
    __syncthreads();
    {
        float4* og = (float4*)(out + ((size_t)agent * CO + coB) * (OHW * OHW));
        const float4* osrc = (const float4*)s;
        #pragma unroll 4
        for (int i = tid; i < (COCH * OHW * OHW) / 4; i += NTHR) og[i] = osrc[i];
    }
}

// ---------------------------------------------------------------------------
// MLP0 split-K (unchanged)
// ---------------------------------------------------------------------------
#define KSPLIT  8
#define KCHUNK  968

__global__ void mlp0_splitk_kernel(const float* __restrict__ A,
                                   const float* __restrict__ W,
                                   float* __restrict__ Cacc)
{
    __shared__ float As[8 * 68];
    __shared__ float Ws[8 * 128];
    const int t  = threadIdx.x;
    const int kz = blockIdx.x;
    const int m0 = blockIdx.y * 64;
    const int kstart = kz * KCHUNK;
    const int tx = t & 31, ty = t >> 5;

    u64 acc[8][2];
    #pragma unroll
    for (int r = 0; r < 8; r++) { acc[r][0] = 0ull; acc[r][1] = 0ull; }

    for (int kk = 0; kk < KCHUNK; kk += 8) {
        __syncthreads();
        {
            int e = t * 2;
            int m = e >> 3, k = e & 7;
            const float* ap = A + (size_t)(m0 + m) * FLAT + kstart + kk + k;
            As[ k      * 68 + m] = ap[0];
            As[(k + 1) * 68 + m] = ap[1];
        }
        {
            int e = t * 4;
            int k = e >> 7, col = e & 127;
            *(float4*)&Ws[k * 128 + col] =
                *(const float4*)&W[(size_t)(kstart + kk + k) * EDIM + col];
        }
        __syncthreads();
        #pragma unroll
        for (int k = 0; k < 8; k++) {
            u64 B0 = *(const u64*)&Ws[k * 128 + tx * 4];
            u64 B1 = *(const u64*)&Ws[k * 128 + tx * 4 + 2];
            float4 a0 = *(float4*)&As[k * 68 + ty * 8];
            float4 a1 = *(float4*)&As[k * 68 + ty * 8 + 4];
            float av[8] = {a0.x,a0.y,a0.z,a0.w,a1.x,a1.y,a1.z,a1.w};
            #pragma unroll
            for (int r = 0; r < 8; r++) {
                u64 ar = pk1(av[r]);
                acc[r][0] = ffma2(ar, B0, acc[r][0]);
                acc[r][1] = ffma2(ar, B1, acc[r][1]);
            }
        }
    }
    #pragma unroll
    for (int r = 0; r < 8; r++) {
        int m = m0 + ty * 8 + r;
        float v0, v1, v2, v3;
        upk2(acc[r][0], v0, v1);
        upk2(acc[r][1], v2, v3);
        atomicAdd(&Cacc[(size_t)m * EDIM + tx * 4 + 0], v0);
        atomicAdd(&Cacc[(size_t)m * EDIM + tx * 4 + 1], v1);
        atomicAdd(&Cacc[(size_t)m * EDIM + tx * 4 + 2], v2);
        atomicAdd(&Cacc[(size_t)m * EDIM + tx * 4 + 3], v3);
    }
}

// ---------------------------------------------------------------------------
// 32-row x 128 GEMM helper (256 threads)
// ---------------------------------------------------------------------------
__device__ __forceinline__ void gemm32(const float* __restrict__ sIn,
                                       float* __restrict__ sOut,
                                       float* __restrict__ sW,
                                       const float* __restrict__ W,
                                       const float* __restrict__ bias,
                                       int relu, int t)
{
    __syncthreads();
    for (int i = t * 4; i < 128 * 128; i += 1024)
        *(float4*)&sW[i] = *(const float4*)&W[i];
    __syncthreads();

    const int tx = t & 31;
    const int ry = (t >> 5) * 4;
    u64 acc[4][2];
    u64 b0i = bias ? pk2(bias[tx*4+0], bias[tx*4+1]) : 0ull;
    u64 b1i = bias ? pk2(bias[tx*4+2], bias[tx*4+3]) : 0ull;
    #pragma unroll
    for (int r = 0; r < 4; r++) { acc[r][0] = b0i; acc[r][1] = b1i; }

    #pragma unroll 4
    for (int k = 0; k < 128; k++) {
        u64 B0 = *(const u64*)&sW[k * 128 + tx * 4];
        u64 B1 = *(const u64*)&sW[k * 128 + tx * 4 + 2];
        #pragma unroll
        for (int r = 0; r < 4; r++) {
            u64 ar = pk1(sIn[(ry + r) * 128 + k]);
            acc[r][0] = ffma2(ar, B0, acc[r][0]);
            acc[r][1] = ffma2(ar, B1, acc[r][1]);
        }
    }
    #pragma unroll
    for (int r = 0; r < 4; r++) {
        float v[4];
        upk2(acc[r][0], v[0], v[1]);
        upk2(acc[r][1], v[2], v[3]);
        #pragma unroll
        for (int c = 0; c < 4; c++)
            if (relu) v[c] = fmaxf(v[c], 0.0f);
        *(float4*)&sOut[(ry + r) * 128 + tx * 4] = *(float4*)v;
    }
}

// ---------------------------------------------------------------------------
// K1: pre-GCN chain, grid = 64, 32-row tiles
// ---------------------------------------------------------------------------
__global__ __launch_bounds__(256, 1)
void pre_gcn_kernel(const float* __restrict__ acc0,
                    const float* __restrict__ mb0,
                    const float* __restrict__ mw1, const float* __restrict__ mb1,
                    const float* __restrict__ mw2, const float* __restrict__ mb2,
                    const float* __restrict__ gw,
                    float* __restrict__ h)
{
    extern __shared__ float s[];
    float* sA = s;
    float* sB = s + 4096;
    float* sW = s + 8192;
    const int t = threadIdx.x;
    const size_t base = (size_t)blockIdx.x * 32 * EDIM;

    for (int i = t; i < 4096; i += 256) {
        int k = i & 127;
        sA[i] = fmaxf(acc0[base + i] + mb0[k], 0.0f);
    }

    gemm32(sA, sB, sW, mw1, mb1, 1, t);
    gemm32(sB, sA, sW, mw2, mb2, 0, t);
    gemm32(sA, sB, sW, gw,  nullptr, 0, t);

    __syncthreads();
    for (int i = t; i < 4096; i += 256) h[base + i] = sB[i];
}

// ---------------------------------------------------------------------------
// K2: GCN aggregation + DQN head, grid = (32, 2)
// ---------------------------------------------------------------------------
__global__ __launch_bounds__(256, 1)
void gcn_tail_kernel(const float* __restrict__ h,
                     const float* __restrict__ gb,
                     const float* __restrict__ fw0, const float* __restrict__ fb0,
                     const float* __restrict__ fw1, const float* __restrict__ fb1,
                     const float* __restrict__ fw2, const float* __restrict__ fb2,
                     const float* __restrict__ adj,
                     const int* __restrict__ inact,
                     float* __restrict__ out)
{
    extern __shared__ float s[];
    float* sH = s;
    float* sX = s + 8192;
    float* sY = s + 12288;
    float* sW = s + 16384;
    const int b = blockIdx.x, t = threadIdx.x;
    const int j0 = blockIdx.y * 32;
    const size_t row0 = (size_t)b * NAGENT;

    for (int i = t; i < 8192; i += 256) sH[i] = h[row0 * EDIM + i];
    for (int i = t; i < 4096; i += 256) sW[i] = adj[(size_t)b * 4096 + i];
    __syncthreads();
    if (t < 64) {
        float d = 0.f;
        for (int i = 0; i < 64; i++) d += sW[i * 64 + t];
        sW[4096 + t] = (d > 0.f) ? rsqrtf(fmaxf(d, 1e-30f)) : 0.f;
    }
    __syncthreads();
    for (int i = t; i < 4096; i += 256) {
        int r = i >> 6, c = i & 63;
        sW[i] *= sW[4096 + r] * sW[4096 + c];
    }
    __syncthreads();
    for (int o = t; o < 4096; o += 256) {
        int jl = o >> 7, d = o & 127;
        int j = j0 + jl;
        float a = gb[d];
        #pragma unroll 8
        for (int i = 0; i < 64; i++)
            a = fmaf(sW[i * 64 + j], sH[i * 128 + d], a);
        sX[o] = a;
    }

    gemm32(sX, sY, sW, fw0, fb0, 1, t);
    gemm32(sY, sX, sW, fw1, fb1, 1, t);

    __syncthreads();
    for (int p = t; p < 32 * ADIM; p += 256) {
        int row = p / ADIM, a = p - row * ADIM;
        float acc = fb2[a];
        #pragma unroll 8
        for (int k = 0; k < EDIM; k++)
            acc = fmaf(sX[row * 128 + k], __ldg(&fw2[k * ADIM + a]), acc);
        size_t grow = row0 + j0 + row;
        bool z = (inact[grow] != 0);
        out[grow * ADIM + a] = z ? 0.f : acc;
    }
}

__global__ void zero_kernel(float* __restrict__ p, int n)
{
    int i = blockIdx.x * blockDim.x + threadIdx.x;
    if (i < n) p[i] = 0.f;
}

// ---------------------------------------------------------------------------
// Launch
// ---------------------------------------------------------------------------
extern "C" void kernel_launch(void* const* d_in, const int* in_sizes, int n_in,
                              void* d_out, int out_size)
{
    (void)in_sizes; (void)n_in; (void)out_size;
    const float* states = (const float*)d_in[0];
    const float* adj    = (const float*)d_in[1];
    const int*   inact  = (const int*)d_in[2];
    const float* cw0 = (const float*)d_in[3];  const float* cb0 = (const float*)d_in[4];
    const float* cw1 = (const float*)d_in[5];  const float* cb1 = (const float*)d_in[6];
    const float* cw2 = (const float*)d_in[7];  const float* cb2 = (const float*)d_in[8];
    const float* cw3 = (const float*)d_in[9];  const float* cb3 = (const float*)d_in[10];
    const float* mw0 = (const float*)d_in[11]; const float* mb0 = (const float*)d_in[12];
    const float* mw1 = (const float*)d_in[13]; const float* mb1 = (const float*)d_in[14];
    const float* mw2 = (const float*)d_in[15]; const float* mb2 = (const float*)d_in[16];
    const float* gw  = (const float*)d_in[17]; const float* gb  = (const float*)d_in[18];
    const float* fw0 = (const float*)d_in[19]; const float* fb0 = (const float*)d_in[20];
    const float* fw1 = (const float*)d_in[21]; const float* fb1 = (const float*)d_in[22];
    const float* fw2 = (const float*)d_in[23]; const float* fb2 = (const float*)d_in[24];
    float* out = (float*)d_out;

    float *p_a0, *p_a1, *p_a2, *p_flat, *p_acc0, *p_h;
    cudaGetSymbolAddress((void**)&p_a0,   g_a0);
    cudaGetSymbolAddress((void**)&p_a1,   g_a1);
    cudaGetSymbolAddress((void**)&p_a2,   g_a2);
    cudaGetSymbolAddress((void**)&p_flat, g_flat);
    cudaGetSymbolAddress((void**)&p_acc0, g_acc0);
    cudaGetSymbolAddress((void**)&p_h,    g_h);

    const int smem0 = 16*30*30*4 + (8*16*9)*8;   // 66816
    const int smem1 = 16*28*28*4 + (8*16*9)*8;   // 59392
    const int smem2 = 32*26*26*4 + (8*32*9)*8;   // 104960
    const int smem3 = 16*24*24*4 + (8*16*9)*8;   // 46080
    const int preSmem  = (4096 + 4096 + 16384) * 4;
    const int tailSmem = (8192 + 4096 + 4096 + 16384) * 4;

    cudaFuncSetAttribute((const void*)conv_stage_kernel<16,16,16,30,28>,
                         cudaFuncAttributeMaxDynamicSharedMemorySize, smem0);
    cudaFuncSetAttribute((const void*)conv_stage_kernel<16,32,16,28,26>,
                         cudaFuncAttributeMaxDynamicSharedMemorySize, smem1);
    cudaFuncSetAttribute((const void*)conv_stage_kernel<32,16,16,26,24>,
                         cudaFuncAttributeMaxDynamicSharedMemorySize, smem2);
    cudaFuncSetAttribute((const void*)conv_stage_kernel<16,16,16,24,22>,
                         cudaFuncAttributeMaxDynamicSharedMemorySize, smem3);
    cudaFuncSetAttribute(pre_gcn_kernel,  cudaFuncAttributeMaxDynamicSharedMemorySize, preSmem);
    cudaFuncSetAttribute(gcn_tail_kernel, cudaFuncAttributeMaxDynamicSharedMemorySize, tailSmem);

    zero_kernel<<<(BN*EDIM + 255)/256, 256>>>(p_acc0, BN*EDIM);

    conv_stage_kernel<16,16,16,30,28><<<dim3(BN,1), 224, smem0>>>(states, p_a0, cw0, cb0);
    conv_stage_kernel<16,32,16,28,26><<<dim3(BN,2), 208, smem1>>>(p_a0,   p_a1, cw1, cb1);
    conv_stage_kernel<32,16,16,26,24><<<dim3(BN,1), 192, smem2>>>(p_a1,   p_a2, cw2, cb2);
    conv_stage_kernel<16,16,16,24,22><<<dim3(BN,1), 176, smem3>>>(p_a2, p_flat, cw3, cb3);

    mlp0_splitk_kernel<<<dim3(KSPLIT, BN/64), 256>>>(p_flat, mw0, p_acc0);

    pre_gcn_kernel<<<BN/32, 256, preSmem>>>(p_acc0, mb0, mw1, mb1, mw2, mb2, gw, p_h);

    gcn_tail_kernel<<<dim3(BATCH, 2), 256, tailSmem>>>(p_h, gb, fw0, fb0, fw1, fb1,
                                                       fw2, fb2, adj, inact, out);
}

// round 14
// speedup vs baseline: 1.6192x; 1.0128x over previous
#include <cuda_runtime.h>
#include <cuda_bf16.h>
#include <cstdint>

// ---------------------------------------------------------------------------
// Problem constants
// ---------------------------------------------------------------------------
#define BATCH   32
#define NAGENT  64
#define BN      2048
#define CIN0    16
#define HW0     30
#define FLAT    7744
#define EDIM    128
#define ADIM    5

// ---------------------------------------------------------------------------
// Scratch (activations between conv stages live in gmem / L2)
// ---------------------------------------------------------------------------
__device__ float g_a0   [ (size_t)BN * 16 * 28 * 28 ];
__device__ float g_a1   [ (size_t)BN * 32 * 26 * 26 ];
__device__ float g_a2   [ (size_t)BN * 16 * 24 * 24 ];
__device__ float g_flat [ (size_t)BN * FLAT ];
__device__ float g_acc0 [ BN * EDIM ];
__device__ float g_h    [ BN * EDIM ];

// ---------------------------------------------------------------------------
// f32x2 packed-math helpers
// ---------------------------------------------------------------------------
typedef unsigned long long u64;

__device__ __forceinline__ u64 pk2(float lo, float hi) {
    u64 r; asm("mov.b64 %0, {%1, %2};" : "=l"(r) : "f"(lo), "f"(hi)); return r;
}
__device__ __forceinline__ u64 pk1(float v) {
    u64 r; asm("mov.b64 %0, {%1, %1};" : "=l"(r) : "f"(v)); return r;
}
__device__ __forceinline__ u64 ffma2(u64 a, u64 b, u64 c) {
    u64 d; asm("fma.rn.f32x2 %0, %1, %2, %3;" : "=l"(d) : "l"(a), "l"(b), "l"(c));
    return d;
}
__device__ __forceinline__ void upk2(u64 v, float& lo, float& hi) {
    asm("mov.b64 {%0, %1}, %2;" : "=f"(lo), "=f"(hi) : "l"(v));
}

// ---------------------------------------------------------------------------
// Per-stage conv kernel (R13 body) with CI PHASING: input planes stream
// through smem in chunks of CICH, halving smem for CI=32 stages so the
// register-file occupancy limit (4 CTAs/SM) becomes reachable.
//  grid = (BN, CO/COCH), block = (COCH/2)*OHW, ONE item per thread.
// ---------------------------------------------------------------------------
template<int CI, int CICH, int CO, int COCH, int IHW, int OHW>
__global__ void __launch_bounds__((COCH/2)*OHW)
conv_stage_kernel(const float* __restrict__ in,   // [BN][CI][IHW][IHW]
                  float* __restrict__ out,        // [BN][CO][OHW][OHW]
                  const float* __restrict__ w,    // [CO][CI][9]
                  const float* __restrict__ bias) // [CO]
{
    extern __shared__ float s[];
    u64* wpk = (u64*)(s + CICH * IHW * IHW);
    const int agent = blockIdx.x;
    const int coB   = blockIdx.y * COCH;
    const int tid   = threadIdx.x;
    constexpr int NTHR = (COCH / 2) * OHW;
    constexpr int PER  = CI * 9;      // full weight stride (gmem)
    constexpr int PERC = CICH * 9;    // packed per-phase stride (smem)
    static_assert(COCH * OHW * OHW <= CICH * IHW * IHW, "output must fit input region");
    static_assert((IHW % 2) == 0 && (OHW % 2) == 0, "pair loads need even sizes");
    static_assert(CI % CICH == 0, "CI phases");

    const int co2 = tid / OHW;
    const int y   = tid - co2 * OHW;

    u64 acc[OHW];
    u64 binit = pk2(__ldg(&bias[coB + 2 * co2]), __ldg(&bias[coB + 2 * co2 + 1]));
    #pragma unroll
    for (int x = 0; x < OHW; x++) acc[x] = binit;

    #pragma unroll
    for (int cib = 0; cib < CI; cib += CICH) {
        __syncthreads();   // previous phase fully consumed (no-op cost phase 0)
        // Phase load: input planes cib..cib+CICH (coalesced float4)
        {
            const float4* src = (const float4*)(in + ((size_t)agent * CI + cib) * (IHW * IHW));
            float4* dst = (float4*)s;
            #pragma unroll 4
            for (int i = tid; i < (CICH * IHW * IHW) / 4; i += NTHR) dst[i] = src[i];
        }
        // pack this phase's weights into u64 channel-pairs
        for (int i = tid; i < (COCH / 2) * PERC; i += NTHR) {
            int pair = i / PERC;
            int r    = i - pair * PERC;   // ci_local*9 + tap
            wpk[i] = pk2(__ldg(&w[(size_t)(coB + 2 * pair    ) * PER + cib * 9 + r]),
                         __ldg(&w[(size_t)(coB + 2 * pair + 1) * PER + cib * 9 + r]));
        }
        __syncthreads();

        const u64* wp0 = wpk + co2 * PERC;
        for (int ci = 0; ci < CICH; ci++) {
            #pragma unroll
            for (int ky = 0; ky < 3; ky++) {
                const u64* wp = wp0 + ci * 9 + ky * 3;
                u64 W0 = wp[0];
                u64 W1 = wp[1];
                u64 W2 = wp[2];
                const float* r = s + (ci * IHW + y + ky) * IHW;
                u64 p0 = *(const u64*)&r[0];
                float f0, f1; upk2(p0, f0, f1);
                u64 b0 = pk1(f0);
                u64 b1 = pk1(f1);
                #pragma unroll
                for (int x = 0; x < OHW; x += 2) {
                    u64 pr = *(const u64*)&r[x + 2];
                    float g0, g1; upk2(pr, g0, g1);
                    u64 b2a = pk1(g0);
                    u64 b2b = pk1(g1);
                    acc[x]   = ffma2(b0,  W0, acc[x]);
                    acc[x]   = ffma2(b1,  W1, acc[x]);
                    acc[x]   = ffma2(b2a, W2, acc[x]);
                    acc[x+1] = ffma2(b1,  W0, acc[x+1]);
                    acc[x+1] = ffma2(b2a, W1, acc[x+1]);
                    acc[x+1] = ffma2(b2b, W2, acc[x+1]);
                    b0 = b2a; b1 = b2b;
                }
            }
        }
    }

    // Stage outputs in smem (input region dead), then coalesced store
    __syncthreads();
    {
        float* oA = s + (2 * co2 * OHW + y) * OHW;
        float* oB = s + ((2 * co2 + 1) * OHW + y) * OHW;
        #pragma unroll
        for (int x = 0; x < OHW; x++) {
            float lo, hi; upk2(acc[x], lo, hi);
            oA[x] = fmaxf(lo, 0.0f);
            oB[x] = fmaxf(hi, 0.0f);
        }
    }
    __syncthreads();
    {
        float4* og = (float4*)(out + ((size_t)agent * CO + coB) * (OHW * OHW));
        const float4* osrc = (const float4*)s;
        #pragma unroll 4
        for (int i = tid; i < (COCH * OHW * OHW) / 4; i += NTHR) og[i] = osrc[i];
    }
}

// ---------------------------------------------------------------------------
// MLP0 split-K (unchanged)
// ---------------------------------------------------------------------------
#define KSPLIT  8
#define KCHUNK  968

__global__ void mlp0_splitk_kernel(const float* __restrict__ A,
                                   const float* __restrict__ W,
                                   float* __restrict__ Cacc)
{
    __shared__ float As[8 * 68];
    __shared__ float Ws[8 * 128];
    const int t  = threadIdx.x;
    const int kz = blockIdx.x;
    const int m0 = blockIdx.y * 64;
    const int kstart = kz * KCHUNK;
    const int tx = t & 31, ty = t >> 5;

    u64 acc[8][2];
    #pragma unroll
    for (int r = 0; r < 8; r++) { acc[r][0] = 0ull; acc[r][1] = 0ull; }

    for (int kk = 0; kk < KCHUNK; kk += 8) {
        __syncthreads();
        {
            int e = t * 2;
            int m = e >> 3, k = e & 7;
            const float* ap = A + (size_t)(m0 + m) * FLAT + kstart + kk + k;
            As[ k      * 68 + m] = ap[0];
            As[(k + 1) * 68 + m] = ap[1];
        }
        {
            int e = t * 4;
            int k = e >> 7, col = e & 127;
            *(float4*)&Ws[k * 128 + col] =
                *(const float4*)&W[(size_t)(kstart + kk + k) * EDIM + col];
        }
        __syncthreads();
        #pragma unroll
        for (int k = 0; k < 8; k++) {
            u64 B0 = *(const u64*)&Ws[k * 128 + tx * 4];
            u64 B1 = *(const u64*)&Ws[k * 128 + tx * 4 + 2];
            float4 a0 = *(float4*)&As[k * 68 + ty * 8];
            float4 a1 = *(float4*)&As[k * 68 + ty * 8 + 4];
            float av[8] = {a0.x,a0.y,a0.z,a0.w,a1.x,a1.y,a1.z,a1.w};
            #pragma unroll
            for (int r = 0; r < 8; r++) {
                u64 ar = pk1(av[r]);
                acc[r][0] = ffma2(ar, B0, acc[r][0]);
                acc[r][1] = ffma2(ar, B1, acc[r][1]);
            }
        }
    }
    #pragma unroll
    for (int r = 0; r < 8; r++) {
        int m = m0 + ty * 8 + r;
        float v0, v1, v2, v3;
        upk2(acc[r][0], v0, v1);
        upk2(acc[r][1], v2, v3);
        atomicAdd(&Cacc[(size_t)m * EDIM + tx * 4 + 0], v0);
        atomicAdd(&Cacc[(size_t)m * EDIM + tx * 4 + 1], v1);
        atomicAdd(&Cacc[(size_t)m * EDIM + tx * 4 + 2], v2);
        atomicAdd(&Cacc[(size_t)m * EDIM + tx * 4 + 3], v3);
    }
}

// ---------------------------------------------------------------------------
// 32-row x 128 GEMM helper (256 threads)
// ---------------------------------------------------------------------------
__device__ __forceinline__ void gemm32(const float* __restrict__ sIn,
                                       float* __restrict__ sOut,
                                       float* __restrict__ sW,
                                       const float* __restrict__ W,
                                       const float* __restrict__ bias,
                                       int relu, int t)
{
    __syncthreads();
    for (int i = t * 4; i < 128 * 128; i += 1024)
        *(float4*)&sW[i] = *(const float4*)&W[i];
    __syncthreads();

    const int tx = t & 31;
    const int ry = (t >> 5) * 4;
    u64 acc[4][2];
    u64 b0i = bias ? pk2(bias[tx*4+0], bias[tx*4+1]) : 0ull;
    u64 b1i = bias ? pk2(bias[tx*4+2], bias[tx*4+3]) : 0ull;
    #pragma unroll
    for (int r = 0; r < 4; r++) { acc[r][0] = b0i; acc[r][1] = b1i; }

    #pragma unroll 4
    for (int k = 0; k < 128; k++) {
        u64 B0 = *(const u64*)&sW[k * 128 + tx * 4];
        u64 B1 = *(const u64*)&sW[k * 128 + tx * 4 + 2];
        #pragma unroll
        for (int r = 0; r < 4; r++) {
            u64 ar = pk1(sIn[(ry + r) * 128 + k]);
            acc[r][0] = ffma2(ar, B0, acc[r][0]);
            acc[r][1] = ffma2(ar, B1, acc[r][1]);
        }
    }
    #pragma unroll
    for (int r = 0; r < 4; r++) {
        float v[4];
        upk2(acc[r][0], v[0], v[1]);
        upk2(acc[r][1], v[2], v[3]);
        #pragma unroll
        for (int c = 0; c < 4; c++)
            if (relu) v[c] = fmaxf(v[c], 0.0f);
        *(float4*)&sOut[(ry + r) * 128 + tx * 4] = *(float4*)v;
    }
}

// ---------------------------------------------------------------------------
// K1: pre-GCN chain, grid = 64, 32-row tiles
// ---------------------------------------------------------------------------
__global__ __launch_bounds__(256, 1)
void pre_gcn_kernel(const float* __restrict__ acc0,
                    const float* __restrict__ mb0,
                    const float* __restrict__ mw1, const float* __restrict__ mb1,
                    const float* __restrict__ mw2, const float* __restrict__ mb2,
                    const float* __restrict__ gw,
                    float* __restrict__ h)
{
    extern __shared__ float s[];
    float* sA = s;
    float* sB = s + 4096;
    float* sW = s + 8192;
    const int t = threadIdx.x;
    const size_t base = (size_t)blockIdx.x * 32 * EDIM;

    for (int i = t; i < 4096; i += 256) {
        int k = i & 127;
        sA[i] = fmaxf(acc0[base + i] + mb0[k], 0.0f);
    }

    gemm32(sA, sB, sW, mw1, mb1, 1, t);
    gemm32(sB, sA, sW, mw2, mb2, 0, t);
    gemm32(sA, sB, sW, gw,  nullptr, 0, t);

    __syncthreads();
    for (int i = t; i < 4096; i += 256) h[base + i] = sB[i];
}

// ---------------------------------------------------------------------------
// K2: GCN aggregation + DQN head, grid = (32, 2)
// ---------------------------------------------------------------------------
__global__ __launch_bounds__(256, 1)
void gcn_tail_kernel(const float* __restrict__ h,
                     const float* __restrict__ gb,
                     const float* __restrict__ fw0, const float* __restrict__ fb0,
                     const float* __restrict__ fw1, const float* __restrict__ fb1,
                     const float* __restrict__ fw2, const float* __restrict__ fb2,
                     const float* __restrict__ adj,
                     const int* __restrict__ inact,
                     float* __restrict__ out)
{
    extern __shared__ float s[];
    float* sH = s;
    float* sX = s + 8192;
    float* sY = s + 12288;
    float* sW = s + 16384;
    const int b = blockIdx.x, t = threadIdx.x;
    const int j0 = blockIdx.y * 32;
    const size_t row0 = (size_t)b * NAGENT;

    for (int i = t; i < 8192; i += 256) sH[i] = h[row0 * EDIM + i];
    for (int i = t; i < 4096; i += 256) sW[i] = adj[(size_t)b * 4096 + i];
    __syncthreads();
    if (t < 64) {
        float d = 0.f;
        for (int i = 0; i < 64; i++) d += sW[i * 64 + t];
        sW[4096 + t] = (d > 0.f) ? rsqrtf(fmaxf(d, 1e-30f)) : 0.f;
    }
    __syncthreads();
    for (int i = t; i < 4096; i += 256) {
        int r = i >> 6, c = i & 63;
        sW[i] *= sW[4096 + r] * sW[4096 + c];
    }
    __syncthreads();
    for (int o = t; o < 4096; o += 256) {
        int jl = o >> 7, d = o & 127;
        int j = j0 + jl;
        float a = gb[d];
        #pragma unroll 8
        for (int i = 0; i < 64; i++)
            a = fmaf(sW[i * 64 + j], sH[i * 128 + d], a);
        sX[o] = a;
    }

    gemm32(sX, sY, sW, fw0, fb0, 1, t);
    gemm32(sY, sX, sW, fw1, fb1, 1, t);

    __syncthreads();
    for (int p = t; p < 32 * ADIM; p += 256) {
        int row = p / ADIM, a = p - row * ADIM;
        float acc = fb2[a];
        #pragma unroll 8
        for (int k = 0; k < EDIM; k++)
            acc = fmaf(sX[row * 128 + k], __ldg(&fw2[k * ADIM + a]), acc);
        size_t grow = row0 + j0 + row;
        bool z = (inact[grow] != 0);
        out[grow * ADIM + a] = z ? 0.f : acc;
    }
}

__global__ void zero_kernel(float* __restrict__ p, int n)
{
    int i = blockIdx.x * blockDim.x + threadIdx.x;
    if (i < n) p[i] = 0.f;
}

// ---------------------------------------------------------------------------
// Launch
// ---------------------------------------------------------------------------
extern "C" void kernel_launch(void* const* d_in, const int* in_sizes, int n_in,
                              void* d_out, int out_size)
{
    (void)in_sizes; (void)n_in; (void)out_size;
    const float* states = (const float*)d_in[0];
    const float* adj    = (const float*)d_in[1];
    const int*   inact  = (const int*)d_in[2];
    const float* cw0 = (const float*)d_in[3];  const float* cb0 = (const float*)d_in[4];
    const float* cw1 = (const float*)d_in[5];  const float* cb1 = (const float*)d_in[6];
    const float* cw2 = (const float*)d_in[7];  const float* cb2 = (const float*)d_in[8];
    const float* cw3 = (const float*)d_in[9];  const float* cb3 = (const float*)d_in[10];
    const float* mw0 = (const float*)d_in[11]; const float* mb0 = (const float*)d_in[12];
    const float* mw1 = (const float*)d_in[13]; const float* mb1 = (const float*)d_in[14];
    const float* mw2 = (const float*)d_in[15]; const float* mb2 = (const float*)d_in[16];
    const float* gw  = (const float*)d_in[17]; const float* gb  = (const float*)d_in[18];
    const float* fw0 = (const float*)d_in[19]; const float* fb0 = (const float*)d_in[20];
    const float* fw1 = (const float*)d_in[21]; const float* fb1 = (const float*)d_in[22];
    const float* fw2 = (const float*)d_in[23]; const float* fb2 = (const float*)d_in[24];
    float* out = (float*)d_out;

    float *p_a0, *p_a1, *p_a2, *p_flat, *p_acc0, *p_h;
    cudaGetSymbolAddress((void**)&p_a0,   g_a0);
    cudaGetSymbolAddress((void**)&p_a1,   g_a1);
    cudaGetSymbolAddress((void**)&p_a2,   g_a2);
    cudaGetSymbolAddress((void**)&p_flat, g_flat);
    cudaGetSymbolAddress((void**)&p_acc0, g_acc0);
    cudaGetSymbolAddress((void**)&p_h,    g_h);

    // per-stage smem: CICH input planes + packed per-phase weight chunk
    const int smem0 = 16*30*30*4 + (8*16*9)*8;   // 66816
    const int smem1 = 16*28*28*4 + (8*16*9)*8;   // 59392
    const int smem2 = 16*26*26*4 + (8*16*9)*8;   // 52480  (CI phased 32->16)
    const int smem3 = 16*24*24*4 + (8*16*9)*8;   // 46080
    const int preSmem  = (4096 + 4096 + 16384) * 4;
    const int tailSmem = (8192 + 4096 + 4096 + 16384) * 4;

    cudaFuncSetAttribute((const void*)conv_stage_kernel<16,16,16,16,30,28>,
                         cudaFuncAttributeMaxDynamicSharedMemorySize, smem0);
    cudaFuncSetAttribute((const void*)conv_stage_kernel<16,16,32,16,28,26>,
                         cudaFuncAttributeMaxDynamicSharedMemorySize, smem1);
    cudaFuncSetAttribute((const void*)conv_stage_kernel<32,16,16,16,26,24>,
                         cudaFuncAttributeMaxDynamicSharedMemorySize, smem2);
    cudaFuncSetAttribute((const void*)conv_stage_kernel<16,16,16,16,24,22>,
                         cudaFuncAttributeMaxDynamicSharedMemorySize, smem3);
    cudaFuncSetAttribute(pre_gcn_kernel,  cudaFuncAttributeMaxDynamicSharedMemorySize, preSmem);
    cudaFuncSetAttribute(gcn_tail_kernel, cudaFuncAttributeMaxDynamicSharedMemorySize, tailSmem);

    zero_kernel<<<(BN*EDIM + 255)/256, 256>>>(p_acc0, BN*EDIM);

    conv_stage_kernel<16,16,16,16,30,28><<<dim3(BN,1), 224, smem0>>>(states, p_a0, cw0, cb0);
    conv_stage_kernel<16,16,32,16,28,26><<<dim3(BN,2), 208, smem1>>>(p_a0,   p_a1, cw1, cb1);
    conv_stage_kernel<32,16,16,16,26,24><<<dim3(BN,1), 192, smem2>>>(p_a1,   p_a2, cw2, cb2);
    conv_stage_kernel<16,16,16,16,24,22><<<dim3(BN,1), 176, smem3>>>(p_a2, p_flat, cw3, cb3);

    mlp0_splitk_kernel<<<dim3(KSPLIT, BN/64), 256>>>(p_flat, mw0, p_acc0);

    pre_gcn_kernel<<<BN/32, 256, preSmem>>>(p_acc0, mb0, mw1, mb1, mw2, mb2, gw, p_h);

    gcn_tail_kernel<<<dim3(BATCH, 2), 256, tailSmem>>>(p_h, gb, fw0, fb0, fw1, fb1,
                                                       fw2, fb2, adj, inact, out);
}

// round 15
// speedup vs baseline: 1.6462x; 1.0167x over previous
#include <cuda_runtime.h>
#include <cuda_bf16.h>
#include <cstdint>

// ---------------------------------------------------------------------------
// Problem constants
// ---------------------------------------------------------------------------
#define BATCH   32
#define NAGENT  64
#define BN      2048
#define CIN0    16
#define HW0     30
#define FLAT    7744
#define EDIM    128
#define ADIM    5

// ---------------------------------------------------------------------------
// Scratch (activations between conv stages live in gmem / L2)
// ---------------------------------------------------------------------------
__device__ float g_a0   [ (size_t)BN * 16 * 28 * 28 ];
__device__ float g_a1   [ (size_t)BN * 32 * 26 * 26 ];
__device__ float g_a2   [ (size_t)BN * 16 * 24 * 24 ];
__device__ float g_flat [ (size_t)BN * FLAT ];
__device__ float g_acc0 [ BN * EDIM ];
__device__ float g_h    [ BN * EDIM ];

// ---------------------------------------------------------------------------
// f32x2 packed-math helpers
// ---------------------------------------------------------------------------
typedef unsigned long long u64;

__device__ __forceinline__ u64 pk2(float lo, float hi) {
    u64 r; asm("mov.b64 %0, {%1, %2};" : "=l"(r) : "f"(lo), "f"(hi)); return r;
}
__device__ __forceinline__ u64 pk1(float v) {
    u64 r; asm("mov.b64 %0, {%1, %1};" : "=l"(r) : "f"(v)); return r;
}
__device__ __forceinline__ u64 ffma2(u64 a, u64 b, u64 c) {
    u64 d; asm("fma.rn.f32x2 %0, %1, %2, %3;" : "=l"(d) : "l"(a), "l"(b), "l"(c));
    return d;
}
__device__ __forceinline__ void upk2(u64 v, float& lo, float& hi) {
    asm("mov.b64 {%0, %1}, %2;" : "=f"(lo), "=f"(hi) : "l"(v));
}

// ---------------------------------------------------------------------------
// Per-stage conv kernel (R14 body) with MINB min-blocks hint so the
// register allocator matches the smem-derived occupancy limit.
//  grid = (BN, CO/COCH), block = (COCH/2)*OHW, ONE item per thread.
// ---------------------------------------------------------------------------
template<int CI, int CICH, int CO, int COCH, int IHW, int OHW, int MINB>
__global__ void __launch_bounds__((COCH/2)*OHW, MINB)
conv_stage_kernel(const float* __restrict__ in,   // [BN][CI][IHW][IHW]
                  float* __restrict__ out,        // [BN][CO][OHW][OHW]
                  const float* __restrict__ w,    // [CO][CI][9]
                  const float* __restrict__ bias) // [CO]
{
    extern __shared__ float s[];
    u64* wpk = (u64*)(s + CICH * IHW * IHW);
    const int agent = blockIdx.x;
    const int coB   = blockIdx.y * COCH;
    const int tid   = threadIdx.x;
    constexpr int NTHR = (COCH / 2) * OHW;
    constexpr int PER  = CI * 9;      // full weight stride (gmem)
    constexpr int PERC = CICH * 9;    // packed per-phase stride (smem)
    static_assert(COCH * OHW * OHW <= CICH * IHW * IHW, "output must fit input region");
    static_assert((IHW % 2) == 0 && (OHW % 2) == 0, "pair loads need even sizes");
    static_assert(CI % CICH == 0, "CI phases");

    const int co2 = tid / OHW;
    const int y   = tid - co2 * OHW;

    u64 acc[OHW];
    u64 binit = pk2(__ldg(&bias[coB + 2 * co2]), __ldg(&bias[coB + 2 * co2 + 1]));
    #pragma unroll
    for (int x = 0; x < OHW; x++) acc[x] = binit;

    #pragma unroll
    for (int cib = 0; cib < CI; cib += CICH) {
        __syncthreads();
        {
            const float4* src = (const float4*)(in + ((size_t)agent * CI + cib) * (IHW * IHW));
            float4* dst = (float4*)s;
            #pragma unroll 4
            for (int i = tid; i < (CICH * IHW * IHW) / 4; i += NTHR) dst[i] = src[i];
        }
        for (int i = tid; i < (COCH / 2) * PERC; i += NTHR) {
            int pair = i / PERC;
            int r    = i - pair * PERC;
            wpk[i] = pk2(__ldg(&w[(size_t)(coB + 2 * pair    ) * PER + cib * 9 + r]),
                         __ldg(&w[(size_t)(coB + 2 * pair + 1) * PER + cib * 9 + r]));
        }
        __syncthreads();

        const u64* wp0 = wpk + co2 * PERC;
        for (int ci = 0; ci < CICH; ci++) {
            #pragma unroll
            for (int ky = 0; ky < 3; ky++) {
                const u64* wp = wp0 + ci * 9 + ky * 3;
                u64 W0 = wp[0];
                u64 W1 = wp[1];
                u64 W2 = wp[2];
                const float* r = s + (ci * IHW + y + ky) * IHW;
                u64 p0 = *(const u64*)&r[0];
                float f0, f1; upk2(p0, f0, f1);
                u64 b0 = pk1(f0);
                u64 b1 = pk1(f1);
                #pragma unroll
                for (int x = 0; x < OHW; x += 2) {
                    u64 pr = *(const u64*)&r[x + 2];
                    float g0, g1; upk2(pr, g0, g1);
                    u64 b2a = pk1(g0);
                    u64 b2b = pk1(g1);
                    acc[x]   = ffma2(b0,  W0, acc[x]);
                    acc[x]   = ffma2(b1,  W1, acc[x]);
                    acc[x]   = ffma2(b2a, W2, acc[x]);
                    acc[x+1] = ffma2(b1,  W0, acc[x+1]);
                    acc[x+1] = ffma2(b2a, W1, acc[x+1]);
                    acc[x+1] = ffma2(b2b, W2, acc[x+1]);
                    b0 = b2a; b1 = b2b;
                }
            }
        }
    }

    __syncthreads();
    {
        float* oA = s + (2 * co2 * OHW + y) * OHW;
        float* oB = s + ((2 * co2 + 1) * OHW + y) * OHW;
        #pragma unroll
        for (int x = 0; x < OHW; x++) {
            float lo, hi; upk2(acc[x], lo, hi);
            oA[x] = fmaxf(lo, 0.0f);
            oB[x] = fmaxf(hi, 0.0f);
        }
    }
    __syncthreads();
    {
        float4* og = (float4*)(out + ((size_t)agent * CO + coB) * (OHW * OHW));
        const float4* osrc = (const float4*)s;
        #pragma unroll 4
        for (int i = tid; i < (COCH * OHW * OHW) / 4; i += NTHR) og[i] = osrc[i];
    }
}

// ---------------------------------------------------------------------------
// MLP0 split-K (unchanged)
// ---------------------------------------------------------------------------
#define KSPLIT  8
#define KCHUNK  968

__global__ void mlp0_splitk_kernel(const float* __restrict__ A,
                                   const float* __restrict__ W,
                                   float* __restrict__ Cacc)
{
    __shared__ float As[8 * 68];
    __shared__ float Ws[8 * 128];
    const int t  = threadIdx.x;
    const int kz = blockIdx.x;
    const int m0 = blockIdx.y * 64;
    const int kstart = kz * KCHUNK;
    const int tx = t & 31, ty = t >> 5;

    u64 acc[8][2];
    #pragma unroll
    for (int r = 0; r < 8; r++) { acc[r][0] = 0ull; acc[r][1] = 0ull; }

    for (int kk = 0; kk < KCHUNK; kk += 8) {
        __syncthreads();
        {
            int e = t * 2;
            int m = e >> 3, k = e & 7;
            const float* ap = A + (size_t)(m0 + m) * FLAT + kstart + kk + k;
            As[ k      * 68 + m] = ap[0];
            As[(k + 1) * 68 + m] = ap[1];
        }
        {
            int e = t * 4;
            int k = e >> 7, col = e & 127;
            *(float4*)&Ws[k * 128 + col] =
                *(const float4*)&W[(size_t)(kstart + kk + k) * EDIM + col];
        }
        __syncthreads();
        #pragma unroll
        for (int k = 0; k < 8; k++) {
            u64 B0 = *(const u64*)&Ws[k * 128 + tx * 4];
            u64 B1 = *(const u64*)&Ws[k * 128 + tx * 4 + 2];
            float4 a0 = *(float4*)&As[k * 68 + ty * 8];
            float4 a1 = *(float4*)&As[k * 68 + ty * 8 + 4];
            float av[8] = {a0.x,a0.y,a0.z,a0.w,a1.x,a1.y,a1.z,a1.w};
            #pragma unroll
            for (int r = 0; r < 8; r++) {
                u64 ar = pk1(av[r]);
                acc[r][0] = ffma2(ar, B0, acc[r][0]);
                acc[r][1] = ffma2(ar, B1, acc[r][1]);
            }
        }
    }
    #pragma unroll
    for (int r = 0; r < 8; r++) {
        int m = m0 + ty * 8 + r;
        float v0, v1, v2, v3;
        upk2(acc[r][0], v0, v1);
        upk2(acc[r][1], v2, v3);
        atomicAdd(&Cacc[(size_t)m * EDIM + tx * 4 + 0], v0);
        atomicAdd(&Cacc[(size_t)m * EDIM + tx * 4 + 1], v1);
        atomicAdd(&Cacc[(size_t)m * EDIM + tx * 4 + 2], v2);
        atomicAdd(&Cacc[(size_t)m * EDIM + tx * 4 + 3], v3);
    }
}

// ---------------------------------------------------------------------------
// GEMM helpers (256 threads): gemm32 = 4 rows x 4 cols; gemm16 = 2 rows x 4
// ---------------------------------------------------------------------------
__device__ __forceinline__ void gemm32(const float* __restrict__ sIn,
                                       float* __restrict__ sOut,
                                       float* __restrict__ sW,
                                       const float* __restrict__ W,
                                       const float* __restrict__ bias,
                                       int relu, int t)
{
    __syncthreads();
    for (int i = t * 4; i < 128 * 128; i += 1024)
        *(float4*)&sW[i] = *(const float4*)&W[i];
    __syncthreads();

    const int tx = t & 31;
    const int ry = (t >> 5) * 4;
    u64 acc[4][2];
    u64 b0i = bias ? pk2(bias[tx*4+0], bias[tx*4+1]) : 0ull;
    u64 b1i = bias ? pk2(bias[tx*4+2], bias[tx*4+3]) : 0ull;
    #pragma unroll
    for (int r = 0; r < 4; r++) { acc[r][0] = b0i; acc[r][1] = b1i; }

    #pragma unroll 4
    for (int k = 0; k < 128; k++) {
        u64 B0 = *(const u64*)&sW[k * 128 + tx * 4];
        u64 B1 = *(const u64*)&sW[k * 128 + tx * 4 + 2];
        #pragma unroll
        for (int r = 0; r < 4; r++) {
            u64 ar = pk1(sIn[(ry + r) * 128 + k]);
            acc[r][0] = ffma2(ar, B0, acc[r][0]);
            acc[r][1] = ffma2(ar, B1, acc[r][1]);
        }
    }
    #pragma unroll
    for (int r = 0; r < 4; r++) {
        float v[4];
        upk2(acc[r][0], v[0], v[1]);
        upk2(acc[r][1], v[2], v[3]);
        #pragma unroll
        for (int c = 0; c < 4; c++)
            if (relu) v[c] = fmaxf(v[c], 0.0f);
        *(float4*)&sOut[(ry + r) * 128 + tx * 4] = *(float4*)v;
    }
}

__device__ __forceinline__ void gemm16(const float* __restrict__ sIn,
                                       float* __restrict__ sOut,
                                       float* __restrict__ sW,
                                       const float* __restrict__ W,
                                       const float* __restrict__ bias,
                                       int relu, int t)
{
    __syncthreads();
    for (int i = t * 4; i < 128 * 128; i += 1024)
        *(float4*)&sW[i] = *(const float4*)&W[i];
    __syncthreads();

    const int tx = t & 31;
    const int ry = (t >> 5) * 2;
    u64 acc[2][2];
    u64 b0i = bias ? pk2(bias[tx*4+0], bias[tx*4+1]) : 0ull;
    u64 b1i = bias ? pk2(bias[tx*4+2], bias[tx*4+3]) : 0ull;
    #pragma unroll
    for (int r = 0; r < 2; r++) { acc[r][0] = b0i; acc[r][1] = b1i; }

    #pragma unroll 4
    for (int k = 0; k < 128; k++) {
        u64 B0 = *(const u64*)&sW[k * 128 + tx * 4];
        u64 B1 = *(const u64*)&sW[k * 128 + tx * 4 + 2];
        #pragma unroll
        for (int r = 0; r < 2; r++) {
            u64 ar = pk1(sIn[(ry + r) * 128 + k]);
            acc[r][0] = ffma2(ar, B0, acc[r][0]);
            acc[r][1] = ffma2(ar, B1, acc[r][1]);
        }
    }
    #pragma unroll
    for (int r = 0; r < 2; r++) {
        float v[4];
        upk2(acc[r][0], v[0], v[1]);
        upk2(acc[r][1], v[2], v[3]);
        #pragma unroll
        for (int c = 0; c < 4; c++)
            if (relu) v[c] = fmaxf(v[c], 0.0f);
        *(float4*)&sOut[(ry + r) * 128 + tx * 4] = *(float4*)v;
    }
}

// ---------------------------------------------------------------------------
// K1: pre-GCN chain, grid = 128, 16-row tiles (full-chip coverage)
// ---------------------------------------------------------------------------
__global__ __launch_bounds__(256, 1)
void pre_gcn_kernel(const float* __restrict__ acc0,
                    const float* __restrict__ mb0,
                    const float* __restrict__ mw1, const float* __restrict__ mb1,
                    const float* __restrict__ mw2, const float* __restrict__ mb2,
                    const float* __restrict__ gw,
                    float* __restrict__ h)
{
    extern __shared__ float s[];
    float* sA = s;             // 16*128
    float* sB = s + 2048;      // 16*128
    float* sW = s + 4096;      // 128*128
    const int t = threadIdx.x;
    const size_t base = (size_t)blockIdx.x * 16 * EDIM;

    for (int i = t; i < 2048; i += 256) {
        int k = i & 127;
        sA[i] = fmaxf(acc0[base + i] + mb0[k], 0.0f);
    }

    gemm16(sA, sB, sW, mw1, mb1, 1, t);
    gemm16(sB, sA, sW, mw2, mb2, 0, t);
    gemm16(sA, sB, sW, gw,  nullptr, 0, t);

    __syncthreads();
    for (int i = t; i < 2048; i += 256) h[base + i] = sB[i];
}

// ---------------------------------------------------------------------------
// K2: GCN aggregation + DQN head, grid = (32, 2)  (unchanged)
// ---------------------------------------------------------------------------
__global__ __launch_bounds__(256, 1)
void gcn_tail_kernel(const float* __restrict__ h,
                     const float* __restrict__ gb,
                     const float* __restrict__ fw0, const float* __restrict__ fb0,
                     const float* __restrict__ fw1, const float* __restrict__ fb1,
                     const float* __restrict__ fw2, const float* __restrict__ fb2,
                     const float* __restrict__ adj,
                     const int* __restrict__ inact,
                     float* __restrict__ out)
{
    extern __shared__ float s[];
    float* sH = s;
    float* sX = s + 8192;
    float* sY = s + 12288;
    float* sW = s + 16384;
    const int b = blockIdx.x, t = threadIdx.x;
    const int j0 = blockIdx.y * 32;
    const size_t row0 = (size_t)b * NAGENT;

    for (int i = t; i < 8192; i += 256) sH[i] = h[row0 * EDIM + i];
    for (int i = t; i < 4096; i += 256) sW[i] = adj[(size_t)b * 4096 + i];
    __syncthreads();
    if (t < 64) {
        float d = 0.f;
        for (int i = 0; i < 64; i++) d += sW[i * 64 + t];
        sW[4096 + t] = (d > 0.f) ? rsqrtf(fmaxf(d, 1e-30f)) : 0.f;
    }
    __syncthreads();
    for (int i = t; i < 4096; i += 256) {
        int r = i >> 6, c = i & 63;
        sW[i] *= sW[4096 + r] * sW[4096 + c];
    }
    __syncthreads();
    for (int o = t; o < 4096; o += 256) {
        int jl = o >> 7, d = o & 127;
        int j = j0 + jl;
        float a = gb[d];
        #pragma unroll 8
        for (int i = 0; i < 64; i++)
            a = fmaf(sW[i * 64 + j], sH[i * 128 + d], a);
        sX[o] = a;
    }

    gemm32(sX, sY, sW, fw0, fb0, 1, t);
    gemm32(sY, sX, sW, fw1, fb1, 1, t);

    __syncthreads();
    for (int p = t; p < 32 * ADIM; p += 256) {
        int row = p / ADIM, a = p - row * ADIM;
        float acc = fb2[a];
        #pragma unroll 8
        for (int k = 0; k < EDIM; k++)
            acc = fmaf(sX[row * 128 + k], __ldg(&fw2[k * ADIM + a]), acc);
        size_t grow = row0 + j0 + row;
        bool z = (inact[grow] != 0);
        out[grow * ADIM + a] = z ? 0.f : acc;
    }
}

__global__ void zero_kernel(float* __restrict__ p, int n)
{
    int i = blockIdx.x * blockDim.x + threadIdx.x;
    if (i < n) p[i] = 0.f;
}

// ---------------------------------------------------------------------------
// Launch
// ---------------------------------------------------------------------------
extern "C" void kernel_launch(void* const* d_in, const int* in_sizes, int n_in,
                              void* d_out, int out_size)
{
    (void)in_sizes; (void)n_in; (void)out_size;
    const float* states = (const float*)d_in[0];
    const float* adj    = (const float*)d_in[1];
    const int*   inact  = (const int*)d_in[2];
    const float* cw0 = (const float*)d_in[3];  const float* cb0 = (const float*)d_in[4];
    const float* cw1 = (const float*)d_in[5];  const float* cb1 = (const float*)d_in[6];
    const float* cw2 = (const float*)d_in[7];  const float* cb2 = (const float*)d_in[8];
    const float* cw3 = (const float*)d_in[9];  const float* cb3 = (const float*)d_in[10];
    const float* mw0 = (const float*)d_in[11]; const float* mb0 = (const float*)d_in[12];
    const float* mw1 = (const float*)d_in[13]; const float* mb1 = (const float*)d_in[14];
    const float* mw2 = (const float*)d_in[15]; const float* mb2 = (const float*)d_in[16];
    const float* gw  = (const float*)d_in[17]; const float* gb  = (const float*)d_in[18];
    const float* fw0 = (const float*)d_in[19]; const float* fb0 = (const float*)d_in[20];
    const float* fw1 = (const float*)d_in[21]; const float* fb1 = (const float*)d_in[22];
    const float* fw2 = (const float*)d_in[23]; const float* fb2 = (const float*)d_in[24];
    float* out = (float*)d_out;

    float *p_a0, *p_a1, *p_a2, *p_flat, *p_acc0, *p_h;
    cudaGetSymbolAddress((void**)&p_a0,   g_a0);
    cudaGetSymbolAddress((void**)&p_a1,   g_a1);
    cudaGetSymbolAddress((void**)&p_a2,   g_a2);
    cudaGetSymbolAddress((void**)&p_flat, g_flat);
    cudaGetSymbolAddress((void**)&p_acc0, g_acc0);
    cudaGetSymbolAddress((void**)&p_h,    g_h);

    const int smem0 = 16*30*30*4 + (8*16*9)*8;   // 66816
    const int smem1 = 16*28*28*4 + (8*16*9)*8;   // 59392
    const int smem2 = 16*26*26*4 + (8*16*9)*8;   // 52480
    const int smem3 = 16*24*24*4 + (8*16*9)*8;   // 46080
    const int preSmem  = (2048 + 2048 + 16384) * 4;   // 81920
    const int tailSmem = (8192 + 4096 + 4096 + 16384) * 4;

    cudaFuncSetAttribute((const void*)conv_stage_kernel<16,16,16,16,30,28,3>,
                         cudaFuncAttributeMaxDynamicSharedMemorySize, smem0);
    cudaFuncSetAttribute((const void*)conv_stage_kernel<16,16,32,16,28,26,3>,
                         cudaFuncAttributeMaxDynamicSharedMemorySize, smem1);
    cudaFuncSetAttribute((const void*)conv_stage_kernel<32,16,16,16,26,24,4>,
                         cudaFuncAttributeMaxDynamicSharedMemorySize, smem2);
    cudaFuncSetAttribute((const void*)conv_stage_kernel<16,16,16,16,24,22,4>,
                         cudaFuncAttributeMaxDynamicSharedMemorySize, smem3);
    cudaFuncSetAttribute(pre_gcn_kernel,  cudaFuncAttributeMaxDynamicSharedMemorySize, preSmem);
    cudaFuncSetAttribute(gcn_tail_kernel, cudaFuncAttributeMaxDynamicSharedMemorySize, tailSmem);

    zero_kernel<<<(BN*EDIM + 255)/256, 256>>>(p_acc0, BN*EDIM);

    conv_stage_kernel<16,16,16,16,30,28,3><<<dim3(BN,1), 224, smem0>>>(states, p_a0, cw0, cb0);
    conv_stage_kernel<16,16,32,16,28,26,3><<<dim3(BN,2), 208, smem1>>>(p_a0,   p_a1, cw1, cb1);
    conv_stage_kernel<32,16,16,16,26,24,4><<<dim3(BN,1), 192, smem2>>>(p_a1,   p_a2, cw2, cb2);
    conv_stage_kernel<16,16,16,16,24,22,4><<<dim3(BN,1), 176, smem3>>>(p_a2, p_flat, cw3, cb3);

    mlp0_splitk_kernel<<<dim3(KSPLIT, BN/64), 256>>>(p_flat, mw0, p_acc0);

    pre_gcn_kernel<<<BN/16, 256, preSmem>>>(p_acc0, mb0, mw1, mb1, mw2, mb2, gw, p_h);

    gcn_tail_kernel<<<dim3(BATCH, 2), 256, tailSmem>>>(p_h, gb, fw0, fb0, fw1, fb1,
                                                       fw2, fb2, adj, inact, out);
}